// round 1
// baseline (speedup 1.0000x reference)
#include <cuda_runtime.h>

#define BB 128
#define SS 4096
#define CC 64
#define TILE 128
#define NW 8
#define THREADS (NW * 32)

// packed f32x2 FMA (Blackwell): d = a*b + c on two lanes of a 64-bit pair
__device__ __forceinline__ float2 ffma2(float2 a, float2 b, float2 c) {
    float2 d;
    asm("{\n\t"
        ".reg .b64 ra, rb, rc, rd;\n\t"
        "mov.b64 ra, {%2, %3};\n\t"
        "mov.b64 rb, {%4, %5};\n\t"
        "mov.b64 rc, {%6, %7};\n\t"
        "fma.rn.f32x2 rd, ra, rb, rc;\n\t"
        "mov.b64 {%0, %1}, rd;\n\t"
        "}"
        : "=f"(d.x), "=f"(d.y)
        : "f"(a.x), "f"(a.y), "f"(b.x), "f"(b.y), "f"(c.x), "f"(c.y));
    return d;
}

__global__ __launch_bounds__(THREADS) void pk_kernel(
    const float* __restrict__ logits,
    const float* __restrict__ M,
    float* __restrict__ out)
{
    extern __shared__ float dsm[];
    // sp: [TILE+1][CC] log-softmax rows
    float (*sp)[CC] = (float (*)[CC])dsm;
    // sM: [CC][CC/2] float2 pairs (lane j owns d = 2j, 2j+1)
    float2 (*sM)[CC / 2] = (float2 (*)[CC / 2])(dsm + (TILE + 1) * CC);

    const int b    = blockIdx.y;
    const int t0   = blockIdx.x * TILE;
    const int tid  = threadIdx.x;
    const int w    = tid >> 5;
    const int lane = tid & 31;

    const int ntok = min(TILE + 1, SS - t0);   // rows of p needed (129, or 128 for last tile)
    const int nout = min(TILE, SS - 1 - t0);   // outputs this block produces (128, or 127)

    // ---- stage M into smem (float2 layout) ----
    {
        const float2* M2 = (const float2*)M;
        float2* sM2 = (float2*)sM;
        #pragma unroll 4
        for (int i = tid; i < CC * CC / 2; i += THREADS)
            sM2[i] = M2[i];
    }

    // ---- phase 1: log-softmax, one warp per token ----
    const float* lg = logits + ((size_t)b * SS + t0) * CC;
    for (int t = w; t < ntok; t += NW) {
        float x0 = lg[t * CC + lane];
        float x1 = lg[t * CC + lane + 32];
        float m = fmaxf(x0, x1);
        #pragma unroll
        for (int o = 16; o; o >>= 1) m = fmaxf(m, __shfl_xor_sync(0xffffffffu, m, o));
        float s = __expf(x0 - m) + __expf(x1 - m);
        #pragma unroll
        for (int o = 16; o; o >>= 1) s += __shfl_xor_sync(0xffffffffu, s, o);
        float lse = m + __logf(s);
        sp[t][lane]      = x0 - lse;
        sp[t][lane + 32] = x1 - lse;
    }
    __syncthreads();

    // ---- phase 2: loss_i = (p_i @ M) . p_{i+1}, 4 tokens per warp-group ----
    float* outp = out + (size_t)b * (SS - 1) + t0;

    for (int g = w * 4; g < TILE; g += NW * 4) {
        // own-token p in registers for shuffle broadcast
        float pA[4], pB[4];
        #pragma unroll
        for (int t = 0; t < 4; t++) {
            pA[t] = sp[g + t][lane];
            pB[t] = sp[g + t][lane + 32];
        }

        float2 acc[4];
        #pragma unroll
        for (int t = 0; t < 4; t++) acc[t] = make_float2(0.f, 0.f);

        #pragma unroll
        for (int c = 0; c < CC; c++) {
            float2 m2 = sM[c][lane];   // M[c][2*lane], M[c][2*lane+1]
            #pragma unroll
            for (int t = 0; t < 4; t++) {
                float pc = __shfl_sync(0xffffffffu, (c < 32) ? pA[t] : pB[t], c & 31);
                acc[t] = ffma2(make_float2(pc, pc), m2, acc[t]);
            }
        }

        #pragma unroll
        for (int t = 0; t < 4; t++) {
            int i = g + t;
            if (i < nout) {
                float2 pn = ((const float2*)sp[i + 1])[lane];
                float v = acc[t].x * pn.x + acc[t].y * pn.y;
                #pragma unroll
                for (int o = 16; o; o >>= 1) v += __shfl_xor_sync(0xffffffffu, v, o);
                if (lane == 0) outp[i] = v;
            }
        }
    }
}

extern "C" void kernel_launch(void* const* d_in, const int* in_sizes, int n_in,
                              void* d_out, int out_size)
{
    const float* logits = (const float*)d_in[0];
    const float* M      = (const float*)d_in[1];
    float* out          = (float*)d_out;

    size_t smem = (size_t)(TILE + 1) * CC * sizeof(float) + (size_t)CC * CC * sizeof(float);
    cudaFuncSetAttribute(pk_kernel, cudaFuncAttributeMaxDynamicSharedMemorySize, (int)smem);

    dim3 grid(SS / TILE, BB);
    pk_kernel<<<grid, THREADS, smem>>>(logits, M, out);
}